// round 13
// baseline (speedup 1.0000x reference)
#include <cuda_runtime.h>
#include <cuda_fp16.h>
#include <cstdint>
#include <math.h>

// ---------------------------------------------------------------------------
// Problem constants
// ---------------------------------------------------------------------------
constexpr int B_  = 4;
constexpr int L_  = 2048;
constexpr int D_  = 512;
constexpr int H_  = 1024;   // 2*D
constexpr int S_  = 16;
constexpr int M_  = B_ * L_;        // 8192 tokens
constexpr int H2_ = 2 * H_;         // 2048
constexpr int KSP_ = 4;             // split-K factor for the zc GEMM

// ---------------------------------------------------------------------------
// Scratch (device globals; no allocation allowed)
// ---------------------------------------------------------------------------
__device__ float  g_z  [M_ * H2_];
__device__ float  g_p  [M_ * H_];    // gate pre-activation (raw)
__device__ float  g_v  [M_ * H_];    // q, then v in-place
__device__ float  g_uc [M_ * H_];    // float uc (scan)
__device__ float  g_zcp[KSP_ * M_ * 64];   // split-K partials
__device__ float  g_zc [M_ * 64];    // float zc (scan)
__device__ float  g_dt [M_ * H_];
// fp16 copies feeding GEMMs
__device__ __half g_clnh[M_ * D_];
__device__ __half g_uch [M_ * H_];
__device__ __half g_zch [M_ * 64];
__device__ __half g_yvh [M_ * H_];
__device__ __half g_xrh [M_ * D_];
__device__ __half g_wah [H2_ * D_];
__device__ __half g_wgbh[H_ * D_];
__device__ __half g_wgch[H_ * D_];
__device__ __half g_wch [64 * H_];
__device__ __half g_weh [H_ * 32];
__device__ __half g_wih [D_ * H_];

// ---------------------------------------------------------------------------
// Helpers
// ---------------------------------------------------------------------------
__device__ __forceinline__ uint32_t smem_u32(const void* p) {
    uint32_t a;
    asm("{ .reg .u64 t; cvta.to.shared.u64 t, %1; cvt.u32.u64 %0, t; }"
        : "=r"(a) : "l"(p));
    return a;
}
__device__ __forceinline__ void cpa16(uint32_t dst, const void* src) {
    asm volatile("cp.async.cg.shared.global [%0], [%1], 16;"
                 :: "r"(dst), "l"(src));
}
__device__ __forceinline__ void cpa8(uint32_t dst, const void* src) {
    asm volatile("cp.async.ca.shared.global [%0], [%1], 8;"
                 :: "r"(dst), "l"(src));
}
__device__ __forceinline__ float tf32r(float x) {
    uint32_t r;
    asm("cvt.rna.tf32.f32 %0, %1;" : "=r"(r) : "f"(x));
    return __uint_as_float(r);
}
__device__ __forceinline__ void mma_f16_16x8x16(float c[4],
                                                const uint32_t a[4],
                                                const uint32_t b[2]) {
    asm volatile(
        "mma.sync.aligned.m16n8k16.row.col.f32.f16.f16.f32 "
        "{%0,%1,%2,%3}, {%4,%5,%6,%7}, {%8,%9}, {%0,%1,%2,%3};"
        : "+f"(c[0]), "+f"(c[1]), "+f"(c[2]), "+f"(c[3])
        : "r"(a[0]), "r"(a[1]), "r"(a[2]), "r"(a[3]),
          "r"(b[0]), "r"(b[1]));
}

// ---------------------------------------------------------------------------
// Batched fp16 conversion (x + all weight matrices)
// ---------------------------------------------------------------------------
struct RoundJob  { const float* src; __half* dst; int n4; };
struct RoundJobs { RoundJob j[7]; };

__global__ void round_all(RoundJobs jobs)
{
    const RoundJob J = jobs.j[blockIdx.y];
    for (int i = blockIdx.x * blockDim.x + threadIdx.x; i < J.n4;
         i += gridDim.x * blockDim.x) {
        const float4 a = ((const float4*)J.src)[i];
        __half2* o = (__half2*)J.dst + 2 * i;
        o[0] = __floats2half2_rn(a.x, a.y);
        o[1] = __floats2half2_rn(a.z, a.w);
    }
}

// ---------------------------------------------------------------------------
// fp16 mma.sync GEMM:  C[m,n] = sum_k A[m,k] * W[n,k]  (+bias, +epilogue)
// 512 threads / 16 warps (4 wm x 4 wn), block 128 x BN (BN = NT*32),
// warp tile 32 x (NT*8).  NT=4 -> BN=128, <=64 regs, 2 CTAs/SM.
// 4 smem stages, BK = 32 halfs/stage, issue distance 3, ONE sync per
// k-tile (buffer being refilled was consumed before this barrier),
// wait_group 2 keeps 3 k-tiles of prefetch in flight.
// Row stride 20 words: fragment reads bank-conflict-free.
// ACT: 0 identity  1 softplus
//      5 dual plain: cols < H_ -> (W,bias)->C, cols >= H_ -> (W2,bias2)->C2
// KSPLIT > 1: blockIdx.x selects a K-chunk, n0 = 0, C += bx * M_ * ldc.
// ---------------------------------------------------------------------------
template<int ACT, int NT, int KSPLIT>
__global__ __launch_bounds__(512, 2)
void mma_gemm(const __half* __restrict__ A, int lda,
              const __half* __restrict__ W, int ldw,
              const float* __restrict__ bias,
              float* __restrict__ C, int ldc, int K,
              const __half* __restrict__ W2,
              const float* __restrict__ bias2,
              float* __restrict__ C2)
{
    constexpr int BN = NT * 32;              // 128 or 64
    constexpr int SW = 20;                   // row stride in 4B words
    constexpr int NS = 4;                    // pipeline stages
    extern __shared__ uint32_t sm[];
    uint32_t* Asm = sm;                      // [NS][128][SW] words
    uint32_t* Bsm = sm + NS * 128 * SW;      // [NS][BN ][SW] words

    const int tid  = threadIdx.x;
    const int warp = tid >> 5, lane = tid & 31;
    const int gid  = lane >> 2, tig = lane & 3;
    const int wm   = warp & 3,  wn  = warp >> 2;
    const int m0   = blockIdx.y * 128;

    int n0, koff, keff;
    if (KSPLIT > 1) {
        n0   = 0;
        keff = K / KSPLIT;
        koff = blockIdx.x * keff;
        C   += (size_t)blockIdx.x * M_ * ldc;
    } else {
        n0   = blockIdx.x * BN;
        keff = K;
        koff = 0;
    }

    // dual-output column split
    const __half* Wuse = W;
    const float*  buse = bias;
    float*        Cuse = C;
    int n0w = n0;
    if (ACT == 5 && n0 >= H_) {
        Wuse = W2; buse = bias2; Cuse = C2; n0w = n0 - H_;
    }

    const int mbase = wm * 32;
    const int nbase = wn * (NT * 8);

    auto sAw = [&](int st, int row, int w) -> uint32_t* {
        return Asm + (st * 128 + row) * SW + w;
    };
    auto sBw = [&](int st, int row, int w) -> uint32_t* {
        return Bsm + (st * BN + row) * SW + w;
    };

    float c[2][NT][4];
    #pragma unroll
    for (int i = 0; i < 2; i++)
        #pragma unroll
        for (int j = 0; j < NT; j++)
            #pragma unroll
            for (int q = 0; q < 4; q++) c[i][j][q] = 0.f;

    // gmem -> smem load slots (A: 16B/thread; B: 16B (NT=4) or 8B (NT=2))
    const int ar  = tid >> 2;                 // 0..127
    const int acw = (tid & 3) * 4;            // word offset in row
    const __half* aq = A + (size_t)(m0 + ar) * lda + koff + acw * 2;

    const int br  = (NT == 4) ? (tid >> 2) : (tid >> 3);
    const int bcw = (NT == 4) ? (tid & 3) * 4 : (tid & 7) * 2;
    const __half* bq = Wuse + (size_t)(n0w + br) * ldw + koff + bcw * 2;

    uint32_t adst[NS], bdst[NS];
    #pragma unroll
    for (int st = 0; st < NS; st++) {
        adst[st] = smem_u32(sAw(st, ar, acw));
        bdst[st] = smem_u32(sBw(st, br, bcw));
    }

    const int nk = keff >> 5;               // stages of BK=32 halfs

    auto issue_stage = [&](int t) {
        if (t < nk) {
            const int sb = t & (NS - 1);
            cpa16(adst[sb], aq + (size_t)t * 32);
            if (NT == 4) cpa16(bdst[sb], bq + (size_t)t * 32);
            else         cpa8 (bdst[sb], bq + (size_t)t * 32);
        }
        asm volatile("cp.async.commit_group;" ::: "memory");
    };

    issue_stage(0);
    issue_stage(1);
    issue_stage(2);

    for (int kt = 0; kt < nk; ++kt) {
        asm volatile("cp.async.wait_group 2;" ::: "memory");
        __syncthreads();
        // refill buf (kt+3)%4 = stage kt-1's buffer; its consumption is
        // sealed by the barrier above.
        issue_stage(kt + 3);

        const int st = kt & (NS - 1);
        #pragma unroll
        for (int ks = 0; ks < 2; ks++) {        // two K=16 steps
            const int wb = ks * 8;
            uint32_t af[2][4], bf[NT][2];
            #pragma unroll
            for (int ti = 0; ti < 2; ti++) {
                const int m = mbase + 16 * ti + gid;
                af[ti][0] = *sAw(st, m,     wb + tig);
                af[ti][1] = *sAw(st, m + 8, wb + tig);
                af[ti][2] = *sAw(st, m,     wb + tig + 4);
                af[ti][3] = *sAw(st, m + 8, wb + tig + 4);
            }
            #pragma unroll
            for (int tj = 0; tj < NT; tj++) {
                const int n = nbase + 8 * tj + gid;
                bf[tj][0] = *sBw(st, n, wb + tig);
                bf[tj][1] = *sBw(st, n, wb + tig + 4);
            }
            #pragma unroll
            for (int ti = 0; ti < 2; ti++)
                #pragma unroll
                for (int tj = 0; tj < NT; tj++)
                    mma_f16_16x8x16(c[ti][tj], af[ti], bf[tj]);
        }
    }

    // epilogue
    #pragma unroll
    for (int ti = 0; ti < 2; ti++) {
        #pragma unroll
        for (int half = 0; half < 2; half++) {
            const int row = m0 + mbase + 16 * ti + gid + half * 8;
            #pragma unroll
            for (int tj = 0; tj < NT; tj++) {
                const int col = n0w + nbase + 8 * tj + 2 * tig;
                float v0 = c[ti][tj][half * 2 + 0];
                float v1 = c[ti][tj][half * 2 + 1];
                if (bias) { v0 += buse[col]; v1 += buse[col + 1]; }
                if (ACT == 1) {
                    v0 = (v0 > 20.f) ? v0 : log1pf(__expf(v0));
                    v1 = (v1 > 20.f) ? v1 : log1pf(__expf(v1));
                }
                float2 r; r.x = v0; r.y = v1;
                *(float2*)(Cuse + (size_t)row * ldc + col) = r;
            }
        }
    }
}

constexpr int SMEM_NT4 = 4 * (128 + 128) * 20 * 4;   // 81920
constexpr int SMEM_NT2 = 4 * (128 + 64)  * 20 * 4;   // 61440

// ---------------------------------------------------------------------------
// Reduce split-K partials; writes float zc (scan) + fp16 zch (dt GEMM)
// ---------------------------------------------------------------------------
__global__ void zc_reduce(const float* __restrict__ zp,
                          float* __restrict__ zc,
                          __half* __restrict__ zch)
{
    const int idx = blockIdx.x * blockDim.x + threadIdx.x;   // float4 index
    if (idx >= M_ * 64 / 4) return;
    const float4* p0 = (const float4*)zp + idx;
    float4 a = p0[0];
    #pragma unroll
    for (int j = 1; j < KSP_; j++) {
        const float4 bq = p0[(size_t)j * (M_ * 64 / 4)];
        a.x += bq.x; a.y += bq.y; a.z += bq.z; a.w += bq.w;
    }
    __half2* oh = (__half2*)zch + 2 * idx;
    oh[0] = __floats2half2_rn(a.x, a.y);
    oh[1] = __floats2half2_rn(a.z, a.w);
    a.x = tf32r(a.x); a.y = tf32r(a.y); a.z = tf32r(a.z); a.w = tf32r(a.w);
    ((float4*)zc)[idx] = a;
}

// ---------------------------------------------------------------------------
// LayerNorm over D=512, one block (256 threads) per token -> fp16 output
// ---------------------------------------------------------------------------
__global__ void ln_kernel(const float* __restrict__ ctx,
                          const float* __restrict__ w,
                          const float* __restrict__ b,
                          __half* __restrict__ out)
{
    __shared__ float red[32];
    const int m = blockIdx.x;
    const int t = threadIdx.x;
    const float* xr = ctx + (size_t)m * D_;
    float v0 = xr[t], v1 = xr[t + 256];

    float s = v0 + v1;
    #pragma unroll
    for (int o = 16; o; o >>= 1) s += __shfl_xor_sync(0xffffffffu, s, o);
    if ((t & 31) == 0) red[t >> 5] = s;
    __syncthreads();
    if (t < 32) {
        float r = (t < 8) ? red[t] : 0.f;
        #pragma unroll
        for (int o = 4; o; o >>= 1) r += __shfl_xor_sync(0xffffffffu, r, o);
        if (t == 0) red[0] = r;
    }
    __syncthreads();
    const float mu = red[0] * (1.f / D_);
    const float d0 = v0 - mu, d1 = v1 - mu;

    float sq = d0 * d0 + d1 * d1;
    #pragma unroll
    for (int o = 16; o; o >>= 1) sq += __shfl_xor_sync(0xffffffffu, sq, o);
    __syncthreads();
    if ((t & 31) == 0) red[t >> 5] = sq;
    __syncthreads();
    if (t < 32) {
        float r = (t < 8) ? red[t] : 0.f;
        #pragma unroll
        for (int o = 4; o; o >>= 1) r += __shfl_xor_sync(0xffffffffu, r, o);
        if (t == 0) red[0] = r;
    }
    __syncthreads();
    const float inv = rsqrtf(red[0] * (1.f / D_) + 1e-5f);

    __half* orow = out + (size_t)m * D_;
    orow[t]       = __float2half_rn(d0 * inv * w[t]       + b[t]);
    orow[t + 256] = __float2half_rn(d1 * inv * w[t + 256] + b[t + 256]);
}

// ---------------------------------------------------------------------------
// Fused uv + causal depthwise conv3 + SiLU.
// ---------------------------------------------------------------------------
__global__ void uvconv_kernel(const float* __restrict__ Z,
                              const float* __restrict__ P,
                              float* __restrict__ Q,     // becomes v
                              const float* __restrict__ cw,
                              const float* __restrict__ cb,
                              float* __restrict__ uc,
                              __half* __restrict__ uch)
{
    const size_t i4 = (size_t)blockIdx.x * blockDim.x + threadIdx.x;
    if (i4 >= (size_t)M_ * H_ / 4) return;
    const size_t idx = i4 * 4;
    const int    h = (int)(idx % H_);
    const size_t m = idx / H_;
    const int    l = (int)(m % L_);

    const size_t zi = m * H2_ + h;

    float4 u0, u1, u2;
    {
        const float4 p0 = *(const float4*)(P + idx);
        const float4 z0 = *(const float4*)(Z + zi);
        float* up = (float*)&u0; const float* pp = (const float*)&p0;
        const float* zp = (const float*)&z0;
        #pragma unroll
        for (int q = 0; q < 4; q++)
            up[q] = zp[q] * (1.f + 1.f / (1.f + __expf(-pp[q])));
    }
    if (l >= 1) {
        const float4 p1 = *(const float4*)(P + idx - H_);
        const float4 z1q = *(const float4*)(Z + zi - H2_);
        float* up = (float*)&u1; const float* pp = (const float*)&p1;
        const float* zp = (const float*)&z1q;
        #pragma unroll
        for (int q = 0; q < 4; q++)
            up[q] = zp[q] * (1.f + 1.f / (1.f + __expf(-pp[q])));
    } else u1 = make_float4(0.f, 0.f, 0.f, 0.f);
    if (l >= 2) {
        const float4 p2 = *(const float4*)(P + idx - 2 * H_);
        const float4 z2q = *(const float4*)(Z + zi - 2 * H2_);
        float* up = (float*)&u2; const float* pp = (const float*)&p2;
        const float* zp = (const float*)&z2q;
        #pragma unroll
        for (int q = 0; q < 4; q++)
            up[q] = zp[q] * (1.f + 1.f / (1.f + __expf(-pp[q])));
    } else u2 = make_float4(0.f, 0.f, 0.f, 0.f);

    const float* u0p = (const float*)&u0;
    const float* u1p = (const float*)&u1;
    const float* u2p = (const float*)&u2;
    float4 o; float* op = (float*)&o;
    #pragma unroll
    for (int q = 0; q < 4; q++) {
        const float r = cw[(h + q) * 3 + 0] * u2p[q]
                      + cw[(h + q) * 3 + 1] * u1p[q]
                      + cw[(h + q) * 3 + 2] * u0p[q] + cb[h + q];
        op[q] = tf32r(r / (1.f + __expf(-r)));   // silu
    }
    *(float4*)(uc + idx) = o;
    __half2* oh = (__half2*)(uch + idx);
    oh[0] = __floats2half2_rn(o.x, o.y);
    oh[1] = __floats2half2_rn(o.z, o.w);

    // v = z2 + q (in-place over q)
    {
        const float4 qv = *(const float4*)(Q + idx);
        const float4 z2v = *(const float4*)(Z + zi + H_);
        float4 vv;
        vv.x = qv.x + z2v.x; vv.y = qv.y + z2v.y;
        vv.z = qv.z + z2v.z; vv.w = qv.w + z2v.w;
        *(float4*)(Q + idx) = vv;
    }
}

// ---------------------------------------------------------------------------
// Selective scan, chunked (16 steps per chunk). Writes fp16 yv.
// ---------------------------------------------------------------------------
__global__ void scan_kernel(const float* __restrict__ uc,
                            const float* __restrict__ dt,
                            const float* __restrict__ zc,
                            const float* __restrict__ v,
                            const float* __restrict__ f_log,
                            const float* __restrict__ g,
                            __half* __restrict__ yv)
{
    const int wid  = (int)((blockIdx.x * blockDim.x + threadIdx.x) >> 5);
    const int lane = threadIdx.x & 31;
    if (wid >= B_ * H_ / 2) return;
    const int b  = wid / (H_ / 2);
    const int h0 = (wid % (H_ / 2)) * 2;
    const int hl = lane >> 4;
    const int s  = lane & 15;
    const int h  = h0 + hl;

    const float a_hs = -__expf(f_log[h * S_ + s]);
    const float gd   = g[h];
    const float* zcb  = zc + (size_t)b * L_ * 64;
    const size_t baseH = (size_t)b * L_ * H_ + h;

    float bc0[16], dt0, uc0, vv0, du0;
    {
        #pragma unroll
        for (int j = 0; j < 16; j++)
            bc0[j] = zcb[(size_t)j * 64 + 32 + lane];
        const size_t o = baseH + (size_t)s * H_;
        dt0 = dt[o]; uc0 = uc[o]; vv0 = v[o];
        du0 = dt0 * uc0;
    }

    float x = 0.f;

    for (int l0 = 0; l0 < L_; l0 += 16) {
        float bc1[16], dt1, uc1, vv1, du1;
        if (l0 + 16 < L_) {
            #pragma unroll
            for (int j = 0; j < 16; j++)
                bc1[j] = zcb[(size_t)(l0 + 16 + j) * 64 + 32 + lane];
            const size_t o = baseH + (size_t)(l0 + 16 + s) * H_;
            dt1 = dt[o]; uc1 = uc[o]; vv1 = v[o];
            du1 = dt1 * uc1;
        } else { dt1 = uc1 = vv1 = du1 = 0.f; }

        float prod[16];
        #pragma unroll
        for (int j = 0; j < 16; j++) {
            const float dtq = __shfl_sync(0xffffffffu, dt0, hl * 16 + j);
            const float duq = __shfl_sync(0xffffffffu, du0, hl * 16 + j);
            const float bm  = __shfl_sync(0xffffffffu, bc0[j], s);
            const float cm  = __shfl_sync(0xffffffffu, bc0[j], 16 + s);

            const float aa = __expf(dtq * a_hs);
            x = fmaf(aa, x, duq * bm);
            prod[j] = x * cm;
        }

        #pragma unroll
        for (int off = 8; off >= 1; off >>= 1) {
            #pragma unroll
            for (int j = 0; j < off; j++) {
                const float a = prod[j], bq = prod[j + off];
                const float send = (s & off) ? a : bq;
                const float t = __shfl_xor_sync(0xffffffffu, send, off);
                prod[j] = (s & off) ? (bq + t) : (a + t);
            }
        }

        const float sv = vv0 / (1.f + __expf(-vv0));
        yv[baseH + (size_t)(l0 + s) * H_] =
            __float2half_rn((prod[0] + uc0 * gd) * sv);

        #pragma unroll
        for (int j = 0; j < 16; j++) bc0[j] = bc1[j];
        dt0 = dt1; uc0 = uc1; vv0 = vv1; du0 = du1;
    }
}

// ---------------------------------------------------------------------------
// Launch
// ---------------------------------------------------------------------------
extern "C" void kernel_launch(void* const* d_in, const int* in_sizes, int n_in,
                              void* d_out, int out_size)
{
    const float* x      = (const float*)d_in[0];
    const float* ctx    = (const float*)d_in[1];
    const float* Wa     = (const float*)d_in[2];
    const float* ba     = (const float*)d_in[3];
    const float* conv_w = (const float*)d_in[4];
    const float* conv_b = (const float*)d_in[5];
    const float* Wc     = (const float*)d_in[6];
    const float* We     = (const float*)d_in[7];
    const float* be     = (const float*)d_in[8];
    const float* f_log  = (const float*)d_in[9];
    const float* g      = (const float*)d_in[10];
    const float* Wi     = (const float*)d_in[11];
    const float* bi     = (const float*)d_in[12];
    const float* ln_w   = (const float*)d_in[13];
    const float* ln_b   = (const float*)d_in[14];
    const float* Wgb    = (const float*)d_in[15];
    const float* bgb    = (const float*)d_in[16];
    const float* Wgc    = (const float*)d_in[17];
    const float* bgc    = (const float*)d_in[18];
    float* out = (float*)d_out;

    float *z, *p, *v, *uc, *zcp, *zcb, *dtb;
    __half *clnh, *uch, *zch, *yvh, *xrh, *wah, *wgbh, *wgch, *wch, *weh, *wih;
    cudaGetSymbolAddress((void**)&z,    g_z);
    cudaGetSymbolAddress((void**)&p,    g_p);
    cudaGetSymbolAddress((void**)&v,    g_v);
    cudaGetSymbolAddress((void**)&uc,   g_uc);
    cudaGetSymbolAddress((void**)&zcp,  g_zcp);
    cudaGetSymbolAddress((void**)&zcb,  g_zc);
    cudaGetSymbolAddress((void**)&dtb,  g_dt);
    cudaGetSymbolAddress((void**)&clnh, g_clnh);
    cudaGetSymbolAddress((void**)&uch,  g_uch);
    cudaGetSymbolAddress((void**)&zch,  g_zch);
    cudaGetSymbolAddress((void**)&yvh,  g_yvh);
    cudaGetSymbolAddress((void**)&xrh,  g_xrh);
    cudaGetSymbolAddress((void**)&wah,  g_wah);
    cudaGetSymbolAddress((void**)&wgbh, g_wgbh);
    cudaGetSymbolAddress((void**)&wgch, g_wgch);
    cudaGetSymbolAddress((void**)&wch,  g_wch);
    cudaGetSymbolAddress((void**)&weh,  g_weh);
    cudaGetSymbolAddress((void**)&wih,  g_wih);

    cudaFuncSetAttribute(mma_gemm<0,4,1>,
        cudaFuncAttributeMaxDynamicSharedMemorySize, SMEM_NT4);
    cudaFuncSetAttribute(mma_gemm<1,4,1>,
        cudaFuncAttributeMaxDynamicSharedMemorySize, SMEM_NT4);
    cudaFuncSetAttribute(mma_gemm<5,4,1>,
        cudaFuncAttributeMaxDynamicSharedMemorySize, SMEM_NT4);
    cudaFuncSetAttribute(mma_gemm<0,2,KSP_>,
        cudaFuncAttributeMaxDynamicSharedMemorySize, SMEM_NT2);

    // 0. fp16-convert x and all weight matrices
    RoundJobs rj;
    rj.j[0] = { x,   xrh,  M_ * D_   / 4 };
    rj.j[1] = { Wa,  wah,  H2_ * D_  / 4 };
    rj.j[2] = { Wgb, wgbh, H_ * D_   / 4 };
    rj.j[3] = { Wgc, wgch, H_ * D_   / 4 };
    rj.j[4] = { Wc,  wch,  64 * H_   / 4 };
    rj.j[5] = { We,  weh,  H_ * 32   / 4 };
    rj.j[6] = { Wi,  wih,  D_ * H_   / 4 };
    round_all<<<dim3(1024, 7), 256>>>(rj);

    // 1. LayerNorm(ctx) -> fp16
    ln_kernel<<<M_, 256>>>(ctx, ln_w, ln_b, clnh);

    // 2. z = x @ Wa^T + ba                      [8192, 2048]
    mma_gemm<0,4,1><<<dim3(H2_ / 128, M_ / 128), 512, SMEM_NT4>>>(
        xrh, D_, wah, D_, ba, z, H2_, D_,
        nullptr, nullptr, nullptr);

    // 3. merged gate GEMM -> p (cols<H) and q (cols>=H), plain+bias
    mma_gemm<5,4,1><<<dim3(H2_ / 128, M_ / 128), 512, SMEM_NT4>>>(
        clnh, D_, wgbh, D_, bgb, p, H_, D_,
        wgch, bgc, v);

    // 4. fused uv + conv + silu -> uc (f32), uch (f16), v in-place
    uvconv_kernel<<<(int)(((size_t)M_ * H_ / 4 + 255) / 256), 256>>>(
        z, p, v, conv_w, conv_b, uc, uch);

    // 5. zc = uc @ Wc^T  (split-K over 4 chunks, then reduce)
    mma_gemm<0,2,KSP_><<<dim3(KSP_, M_ / 128), 512, SMEM_NT2>>>(
        uch, H_, wch, H_, nullptr, zcp, 64, H_,
        nullptr, nullptr, nullptr);
    zc_reduce<<<(M_ * 64 / 4 + 255) / 256, 256>>>(zcp, zcb, zch);

    // 6. dt = softplus(zc[:, :R] @ We^T + be)   [8192, 1024]
    mma_gemm<1,4,1><<<dim3(H_ / 128, M_ / 128), 512, SMEM_NT4>>>(
        zch, 64, weh, 32, be, dtb, H_, 32,
        nullptr, nullptr, nullptr);

    // 7. selective scan (fused skip + silu(v) gate) -> fp16 yv
    scan_kernel<<<(B_ * H_ / 2) / 8, 256>>>(uc, dtb, zcb, v, f_log, g, yvh);

    // 8. out = yv @ Wi^T + bi                   [8192, 512]
    mma_gemm<0,4,1><<<dim3(D_ / 128, M_ / 128), 512, SMEM_NT4>>>(
        yvh, H_, wih, H_, bi, out, D_, H_,
        nullptr, nullptr, nullptr);
}

// round 15
// speedup vs baseline: 1.0546x; 1.0546x over previous
#include <cuda_runtime.h>
#include <cuda_fp16.h>
#include <cstdint>
#include <math.h>

// ---------------------------------------------------------------------------
// Problem constants
// ---------------------------------------------------------------------------
constexpr int B_  = 4;
constexpr int L_  = 2048;
constexpr int D_  = 512;
constexpr int H_  = 1024;   // 2*D
constexpr int S_  = 16;
constexpr int M_  = B_ * L_;        // 8192 tokens
constexpr int H2_ = 2 * H_;         // 2048
constexpr int KSP_ = 4;             // split-K factor for the zc GEMM

// ---------------------------------------------------------------------------
// Scratch (device globals; no allocation allowed)
// ---------------------------------------------------------------------------
__device__ float  g_zcp[KSP_ * M_ * 64];   // split-K partials (float)
__device__ float  g_zc [M_ * 64];          // float zc (scan)
// fp16 intermediates
__device__ __half g_zh  [M_ * H2_];  // z = x@Wa + ba
__device__ __half g_ph  [M_ * H_];   // gate pre-activation
__device__ __half g_vh  [M_ * H_];   // q, then v in-place
__device__ __half g_dth [M_ * H_];   // dt (softplus output)
__device__ __half g_clnh[M_ * D_];
__device__ __half g_uch [M_ * H_];
__device__ __half g_zch [M_ * 64];
__device__ __half g_yvh [M_ * H_];
__device__ __half g_xrh [M_ * D_];
__device__ __half g_wah [H2_ * D_];
__device__ __half g_wgbh[H_ * D_];
__device__ __half g_wgch[H_ * D_];
__device__ __half g_wch [64 * H_];
__device__ __half g_weh [H_ * 32];
__device__ __half g_wih [D_ * H_];

// ---------------------------------------------------------------------------
// Helpers
// ---------------------------------------------------------------------------
__device__ __forceinline__ uint32_t smem_u32(const void* p) {
    uint32_t a;
    asm("{ .reg .u64 t; cvta.to.shared.u64 t, %1; cvt.u32.u64 %0, t; }"
        : "=r"(a) : "l"(p));
    return a;
}
__device__ __forceinline__ void cpa16(uint32_t dst, const void* src) {
    asm volatile("cp.async.cg.shared.global [%0], [%1], 16;"
                 :: "r"(dst), "l"(src));
}
__device__ __forceinline__ void cpa8(uint32_t dst, const void* src) {
    asm volatile("cp.async.ca.shared.global [%0], [%1], 8;"
                 :: "r"(dst), "l"(src));
}
__device__ __forceinline__ float tf32r(float x) {
    uint32_t r;
    asm("cvt.rna.tf32.f32 %0, %1;" : "=r"(r) : "f"(x));
    return __uint_as_float(r);
}
__device__ __forceinline__ float4 ld4h(const __half* p) {
    const __half2* p2 = (const __half2*)p;
    const float2 fa = __half22float2(p2[0]);
    const float2 fb = __half22float2(p2[1]);
    return make_float4(fa.x, fa.y, fb.x, fb.y);
}
__device__ __forceinline__ void mma_f16_16x8x16(float c[4],
                                                const uint32_t a[4],
                                                const uint32_t b[2]) {
    asm volatile(
        "mma.sync.aligned.m16n8k16.row.col.f32.f16.f16.f32 "
        "{%0,%1,%2,%3}, {%4,%5,%6,%7}, {%8,%9}, {%0,%1,%2,%3};"
        : "+f"(c[0]), "+f"(c[1]), "+f"(c[2]), "+f"(c[3])
        : "r"(a[0]), "r"(a[1]), "r"(a[2]), "r"(a[3]),
          "r"(b[0]), "r"(b[1]));
}

// ---------------------------------------------------------------------------
// Batched fp16 conversion (x + all weight matrices)
// ---------------------------------------------------------------------------
struct RoundJob  { const float* src; __half* dst; int n4; };
struct RoundJobs { RoundJob j[7]; };

__global__ void round_all(RoundJobs jobs)
{
    const RoundJob J = jobs.j[blockIdx.y];
    for (int i = blockIdx.x * blockDim.x + threadIdx.x; i < J.n4;
         i += gridDim.x * blockDim.x) {
        const float4 a = ((const float4*)J.src)[i];
        __half2* o = (__half2*)J.dst + 2 * i;
        o[0] = __floats2half2_rn(a.x, a.y);
        o[1] = __floats2half2_rn(a.z, a.w);
    }
}

// ---------------------------------------------------------------------------
// fp16 mma.sync GEMM:  C[m,n] = sum_k A[m,k] * W[n,k]  (+bias, +epilogue)
// R10-best geometry: 512 threads / 16 warps (4x4), block 128x(NT*32),
// warp tile 32x(NT*8), BK=32 halfs, 2 smem stages, row stride 20 words.
// TC = output type (float or __half).
// ACT: 0 identity  1 softplus
//      5 dual plain: cols < H_ -> (W,bias)->C, cols >= H_ -> (W2,bias2)->C2
// KSPLIT > 1: blockIdx.x selects a K-chunk, n0 = 0, C += bx * M_ * ldc.
// ---------------------------------------------------------------------------
template<int ACT, int NT, int KSPLIT, typename TC>
__global__ __launch_bounds__(512, 2)
void mma_gemm(const __half* __restrict__ A, int lda,
              const __half* __restrict__ W, int ldw,
              const float* __restrict__ bias,
              TC* __restrict__ C, int ldc, int K,
              const __half* __restrict__ W2,
              const float* __restrict__ bias2,
              TC* __restrict__ C2)
{
    constexpr int BN = NT * 32;              // 128 or 64
    constexpr int SW = 20;                   // row stride in 4B words
    extern __shared__ uint32_t sm[];
    uint32_t* Asm = sm;                      // [2][128][SW] words
    uint32_t* Bsm = sm + 2 * 128 * SW;       // [2][BN ][SW] words

    const int tid  = threadIdx.x;
    const int warp = tid >> 5, lane = tid & 31;
    const int gid  = lane >> 2, tig = lane & 3;
    const int wm   = warp & 3,  wn  = warp >> 2;
    const int m0   = blockIdx.y * 128;

    int n0, koff, keff;
    if (KSPLIT > 1) {
        n0   = 0;
        keff = K / KSPLIT;
        koff = blockIdx.x * keff;
        C   += (size_t)blockIdx.x * M_ * ldc;
    } else {
        n0   = blockIdx.x * BN;
        keff = K;
        koff = 0;
    }

    // dual-output column split
    const __half* Wuse = W;
    const float*  buse = bias;
    TC*           Cuse = C;
    int n0w = n0;
    if (ACT == 5 && n0 >= H_) {
        Wuse = W2; buse = bias2; Cuse = C2; n0w = n0 - H_;
    }

    const int mbase = wm * 32;
    const int nbase = wn * (NT * 8);

    auto sAw = [&](int st, int row, int w) -> uint32_t* {
        return Asm + (st * 128 + row) * SW + w;
    };
    auto sBw = [&](int st, int row, int w) -> uint32_t* {
        return Bsm + (st * BN + row) * SW + w;
    };

    float c[2][NT][4];
    #pragma unroll
    for (int i = 0; i < 2; i++)
        #pragma unroll
        for (int j = 0; j < NT; j++)
            #pragma unroll
            for (int q = 0; q < 4; q++) c[i][j][q] = 0.f;

    // gmem -> smem load slots (A: 16B/thread; B: 16B (NT=4) or 8B (NT=2))
    const int ar  = tid >> 2;                 // 0..127
    const int acw = (tid & 3) * 4;            // word offset in row
    const __half* aq = A + (size_t)(m0 + ar) * lda + koff + acw * 2;

    const int br  = (NT == 4) ? (tid >> 2) : (tid >> 3);
    const int bcw = (NT == 4) ? (tid & 3) * 4 : (tid & 7) * 2;
    const __half* bq = Wuse + (size_t)(n0w + br) * ldw + koff + bcw * 2;

    uint32_t adst[2], bdst[2];
    #pragma unroll
    for (int st = 0; st < 2; st++) {
        adst[st] = smem_u32(sAw(st, ar, acw));
        bdst[st] = smem_u32(sBw(st, br, bcw));
    }

    const int nk = keff >> 5;               // stages of BK=32 halfs

    auto issue_stage = [&](int t) {
        if (t < nk) {
            const int sb = t & 1;
            cpa16(adst[sb], aq + (size_t)t * 32);
            if (NT == 4) cpa16(bdst[sb], bq + (size_t)t * 32);
            else         cpa8 (bdst[sb], bq + (size_t)t * 32);
        }
        asm volatile("cp.async.commit_group;" ::: "memory");
    };

    issue_stage(0);
    issue_stage(1);

    for (int kt = 0; kt < nk; ++kt) {
        if (kt < nk - 1)
            asm volatile("cp.async.wait_group 1;" ::: "memory");
        else
            asm volatile("cp.async.wait_group 0;" ::: "memory");
        __syncthreads();
        const int st = kt & 1;

        #pragma unroll
        for (int ks = 0; ks < 2; ks++) {        // two K=16 steps
            const int wb = ks * 8;
            uint32_t af[2][4], bf[NT][2];
            #pragma unroll
            for (int ti = 0; ti < 2; ti++) {
                const int m = mbase + 16 * ti + gid;
                af[ti][0] = *sAw(st, m,     wb + tig);
                af[ti][1] = *sAw(st, m + 8, wb + tig);
                af[ti][2] = *sAw(st, m,     wb + tig + 4);
                af[ti][3] = *sAw(st, m + 8, wb + tig + 4);
            }
            #pragma unroll
            for (int tj = 0; tj < NT; tj++) {
                const int n = nbase + 8 * tj + gid;
                bf[tj][0] = *sBw(st, n, wb + tig);
                bf[tj][1] = *sBw(st, n, wb + tig + 4);
            }
            #pragma unroll
            for (int ti = 0; ti < 2; ti++)
                #pragma unroll
                for (int tj = 0; tj < NT; tj++)
                    mma_f16_16x8x16(c[ti][tj], af[ti], bf[tj]);
        }

        __syncthreads();                 // all reads of stage st done
        issue_stage(kt + 2);             // safe to overwrite buffer st
    }

    // epilogue
    #pragma unroll
    for (int ti = 0; ti < 2; ti++) {
        #pragma unroll
        for (int half = 0; half < 2; half++) {
            const int row = m0 + mbase + 16 * ti + gid + half * 8;
            #pragma unroll
            for (int tj = 0; tj < NT; tj++) {
                const int col = n0w + nbase + 8 * tj + 2 * tig;
                float v0 = c[ti][tj][half * 2 + 0];
                float v1 = c[ti][tj][half * 2 + 1];
                if (bias) { v0 += buse[col]; v1 += buse[col + 1]; }
                if (ACT == 1) {
                    v0 = (v0 > 20.f) ? v0 : log1pf(__expf(v0));
                    v1 = (v1 > 20.f) ? v1 : log1pf(__expf(v1));
                }
                if (sizeof(TC) == 2) {
                    *(__half2*)((__half*)Cuse + (size_t)row * ldc + col) =
                        __floats2half2_rn(v0, v1);
                } else {
                    float2 r; r.x = v0; r.y = v1;
                    *(float2*)((float*)Cuse + (size_t)row * ldc + col) = r;
                }
            }
        }
    }
}

constexpr int SMEM_NT4 = (2 * 128 * 20 + 2 * 128 * 20) * 4;   // 40960
constexpr int SMEM_NT2 = (2 * 128 * 20 + 2 * 64  * 20) * 4;   // 30720

// ---------------------------------------------------------------------------
// Reduce split-K partials; writes float zc (scan) + fp16 zch (dt GEMM)
// ---------------------------------------------------------------------------
__global__ void zc_reduce(const float* __restrict__ zp,
                          float* __restrict__ zc,
                          __half* __restrict__ zch)
{
    const int idx = blockIdx.x * blockDim.x + threadIdx.x;   // float4 index
    if (idx >= M_ * 64 / 4) return;
    const float4* p0 = (const float4*)zp + idx;
    float4 a = p0[0];
    #pragma unroll
    for (int j = 1; j < KSP_; j++) {
        const float4 bq = p0[(size_t)j * (M_ * 64 / 4)];
        a.x += bq.x; a.y += bq.y; a.z += bq.z; a.w += bq.w;
    }
    __half2* oh = (__half2*)zch + 2 * idx;
    oh[0] = __floats2half2_rn(a.x, a.y);
    oh[1] = __floats2half2_rn(a.z, a.w);
    a.x = tf32r(a.x); a.y = tf32r(a.y); a.z = tf32r(a.z); a.w = tf32r(a.w);
    ((float4*)zc)[idx] = a;
}

// ---------------------------------------------------------------------------
// LayerNorm over D=512, one block (256 threads) per token -> fp16 output
// ---------------------------------------------------------------------------
__global__ void ln_kernel(const float* __restrict__ ctx,
                          const float* __restrict__ w,
                          const float* __restrict__ b,
                          __half* __restrict__ out)
{
    __shared__ float red[32];
    const int m = blockIdx.x;
    const int t = threadIdx.x;
    const float* xr = ctx + (size_t)m * D_;
    float v0 = xr[t], v1 = xr[t + 256];

    float s = v0 + v1;
    #pragma unroll
    for (int o = 16; o; o >>= 1) s += __shfl_xor_sync(0xffffffffu, s, o);
    if ((t & 31) == 0) red[t >> 5] = s;
    __syncthreads();
    if (t < 32) {
        float r = (t < 8) ? red[t] : 0.f;
        #pragma unroll
        for (int o = 4; o; o >>= 1) r += __shfl_xor_sync(0xffffffffu, r, o);
        if (t == 0) red[0] = r;
    }
    __syncthreads();
    const float mu = red[0] * (1.f / D_);
    const float d0 = v0 - mu, d1 = v1 - mu;

    float sq = d0 * d0 + d1 * d1;
    #pragma unroll
    for (int o = 16; o; o >>= 1) sq += __shfl_xor_sync(0xffffffffu, sq, o);
    __syncthreads();
    if ((t & 31) == 0) red[t >> 5] = sq;
    __syncthreads();
    if (t < 32) {
        float r = (t < 8) ? red[t] : 0.f;
        #pragma unroll
        for (int o = 4; o; o >>= 1) r += __shfl_xor_sync(0xffffffffu, r, o);
        if (t == 0) red[0] = r;
    }
    __syncthreads();
    const float inv = rsqrtf(red[0] * (1.f / D_) + 1e-5f);

    __half* orow = out + (size_t)m * D_;
    orow[t]       = __float2half_rn(d0 * inv * w[t]       + b[t]);
    orow[t + 256] = __float2half_rn(d1 * inv * w[t + 256] + b[t + 256]);
}

// ---------------------------------------------------------------------------
// Fused uv + causal depthwise conv3 + SiLU.  All fp16 I/O, fp32 math.
// u = z1*(1+sigmoid(p)) recomputed at the 3 conv taps; writes
// uch = fp16(silu(conv(u))) and v = z2 + q (in-place over q).
// ---------------------------------------------------------------------------
__global__ void uvconv_kernel(const __half* __restrict__ Z,
                              const __half* __restrict__ P,
                              __half* __restrict__ Q,     // becomes v
                              const float* __restrict__ cw,
                              const float* __restrict__ cb,
                              __half* __restrict__ uch)
{
    const size_t i4 = (size_t)blockIdx.x * blockDim.x + threadIdx.x;
    if (i4 >= (size_t)M_ * H_ / 4) return;
    const size_t idx = i4 * 4;
    const int    h = (int)(idx % H_);
    const size_t m = idx / H_;
    const int    l = (int)(m % L_);

    const size_t zi = m * H2_ + h;

    float u0[4], u1[4], u2[4];
    {
        const float4 p0 = ld4h(P + idx);
        const float4 z0 = ld4h(Z + zi);
        const float* pp = (const float*)&p0;
        const float* zp = (const float*)&z0;
        #pragma unroll
        for (int q = 0; q < 4; q++)
            u0[q] = zp[q] * (1.f + 1.f / (1.f + __expf(-pp[q])));
    }
    if (l >= 1) {
        const float4 p1 = ld4h(P + idx - H_);
        const float4 z1q = ld4h(Z + zi - H2_);
        const float* pp = (const float*)&p1;
        const float* zp = (const float*)&z1q;
        #pragma unroll
        for (int q = 0; q < 4; q++)
            u1[q] = zp[q] * (1.f + 1.f / (1.f + __expf(-pp[q])));
    } else { u1[0] = u1[1] = u1[2] = u1[3] = 0.f; }
    if (l >= 2) {
        const float4 p2 = ld4h(P + idx - 2 * H_);
        const float4 z2q = ld4h(Z + zi - 2 * H2_);
        const float* pp = (const float*)&p2;
        const float* zp = (const float*)&z2q;
        #pragma unroll
        for (int q = 0; q < 4; q++)
            u2[q] = zp[q] * (1.f + 1.f / (1.f + __expf(-pp[q])));
    } else { u2[0] = u2[1] = u2[2] = u2[3] = 0.f; }

    float o[4];
    #pragma unroll
    for (int q = 0; q < 4; q++) {
        const float r = cw[(h + q) * 3 + 0] * u2[q]
                      + cw[(h + q) * 3 + 1] * u1[q]
                      + cw[(h + q) * 3 + 2] * u0[q] + cb[h + q];
        o[q] = r / (1.f + __expf(-r));   // silu
    }
    __half2* oh = (__half2*)(uch + idx);
    oh[0] = __floats2half2_rn(o[0], o[1]);
    oh[1] = __floats2half2_rn(o[2], o[3]);

    // v = z2 + q (in-place over q)
    {
        const float4 qv  = ld4h(Q + idx);
        const float4 z2v = ld4h(Z + zi + H_);
        __half2* vo = (__half2*)(Q + idx);
        vo[0] = __floats2half2_rn(qv.x + z2v.x, qv.y + z2v.y);
        vo[1] = __floats2half2_rn(qv.z + z2v.z, qv.w + z2v.w);
    }
}

// ---------------------------------------------------------------------------
// Selective scan, chunked (16 steps per chunk). fp16 in (uc/dt/v), fp16 out.
// ---------------------------------------------------------------------------
__global__ void scan_kernel(const __half* __restrict__ uc,
                            const __half* __restrict__ dt,
                            const float* __restrict__ zc,
                            const __half* __restrict__ v,
                            const float* __restrict__ f_log,
                            const float* __restrict__ g,
                            __half* __restrict__ yv)
{
    const int wid  = (int)((blockIdx.x * blockDim.x + threadIdx.x) >> 5);
    const int lane = threadIdx.x & 31;
    if (wid >= B_ * H_ / 2) return;
    const int b  = wid / (H_ / 2);
    const int h0 = (wid % (H_ / 2)) * 2;
    const int hl = lane >> 4;
    const int s  = lane & 15;
    const int h  = h0 + hl;

    const float a_hs = -__expf(f_log[h * S_ + s]);
    const float gd   = g[h];
    const float* zcb  = zc + (size_t)b * L_ * 64;
    const size_t baseH = (size_t)b * L_ * H_ + h;

    float bc0[16], dt0, uc0, vv0, du0;
    {
        #pragma unroll
        for (int j = 0; j < 16; j++)
            bc0[j] = zcb[(size_t)j * 64 + 32 + lane];
        const size_t o = baseH + (size_t)s * H_;
        dt0 = __half2float(dt[o]);
        uc0 = __half2float(uc[o]);
        vv0 = __half2float(v[o]);
        du0 = dt0 * uc0;
    }

    float x = 0.f;

    for (int l0 = 0; l0 < L_; l0 += 16) {
        float bc1[16], dt1, uc1, vv1, du1;
        if (l0 + 16 < L_) {
            #pragma unroll
            for (int j = 0; j < 16; j++)
                bc1[j] = zcb[(size_t)(l0 + 16 + j) * 64 + 32 + lane];
            const size_t o = baseH + (size_t)(l0 + 16 + s) * H_;
            dt1 = __half2float(dt[o]);
            uc1 = __half2float(uc[o]);
            vv1 = __half2float(v[o]);
            du1 = dt1 * uc1;
        } else { dt1 = uc1 = vv1 = du1 = 0.f;
                 #pragma unroll
                 for (int j = 0; j < 16; j++) bc1[j] = 0.f; }

        float prod[16];
        #pragma unroll
        for (int j = 0; j < 16; j++) {
            const float dtq = __shfl_sync(0xffffffffu, dt0, hl * 16 + j);
            const float duq = __shfl_sync(0xffffffffu, du0, hl * 16 + j);
            const float bm  = __shfl_sync(0xffffffffu, bc0[j], s);
            const float cm  = __shfl_sync(0xffffffffu, bc0[j], 16 + s);

            const float aa = __expf(dtq * a_hs);
            x = fmaf(aa, x, duq * bm);
            prod[j] = x * cm;
        }

        #pragma unroll
        for (int off = 8; off >= 1; off >>= 1) {
            #pragma unroll
            for (int j = 0; j < off; j++) {
                const float a = prod[j], bq = prod[j + off];
                const float send = (s & off) ? a : bq;
                const float t = __shfl_xor_sync(0xffffffffu, send, off);
                prod[j] = (s & off) ? (bq + t) : (a + t);
            }
        }

        const float sv = vv0 / (1.f + __expf(-vv0));
        yv[baseH + (size_t)(l0 + s) * H_] =
            __float2half_rn((prod[0] + uc0 * gd) * sv);

        #pragma unroll
        for (int j = 0; j < 16; j++) bc0[j] = bc1[j];
        dt0 = dt1; uc0 = uc1; vv0 = vv1; du0 = du1;
    }
}

// ---------------------------------------------------------------------------
// Launch
// ---------------------------------------------------------------------------
extern "C" void kernel_launch(void* const* d_in, const int* in_sizes, int n_in,
                              void* d_out, int out_size)
{
    const float* x      = (const float*)d_in[0];
    const float* ctx    = (const float*)d_in[1];
    const float* Wa     = (const float*)d_in[2];
    const float* ba     = (const float*)d_in[3];
    const float* conv_w = (const float*)d_in[4];
    const float* conv_b = (const float*)d_in[5];
    const float* Wc     = (const float*)d_in[6];
    const float* We     = (const float*)d_in[7];
    const float* be     = (const float*)d_in[8];
    const float* f_log  = (const float*)d_in[9];
    const float* g      = (const float*)d_in[10];
    const float* Wi     = (const float*)d_in[11];
    const float* bi     = (const float*)d_in[12];
    const float* ln_w   = (const float*)d_in[13];
    const float* ln_b   = (const float*)d_in[14];
    const float* Wgb    = (const float*)d_in[15];
    const float* bgb    = (const float*)d_in[16];
    const float* Wgc    = (const float*)d_in[17];
    const float* bgc    = (const float*)d_in[18];
    float* out = (float*)d_out;

    float *zcp, *zcb;
    __half *zh, *ph, *vh, *dth;
    __half *clnh, *uch, *zch, *yvh, *xrh, *wah, *wgbh, *wgch, *wch, *weh, *wih;
    cudaGetSymbolAddress((void**)&zcp,  g_zcp);
    cudaGetSymbolAddress((void**)&zcb,  g_zc);
    cudaGetSymbolAddress((void**)&zh,   g_zh);
    cudaGetSymbolAddress((void**)&ph,   g_ph);
    cudaGetSymbolAddress((void**)&vh,   g_vh);
    cudaGetSymbolAddress((void**)&dth,  g_dth);
    cudaGetSymbolAddress((void**)&clnh, g_clnh);
    cudaGetSymbolAddress((void**)&uch,  g_uch);
    cudaGetSymbolAddress((void**)&zch,  g_zch);
    cudaGetSymbolAddress((void**)&yvh,  g_yvh);
    cudaGetSymbolAddress((void**)&xrh,  g_xrh);
    cudaGetSymbolAddress((void**)&wah,  g_wah);
    cudaGetSymbolAddress((void**)&wgbh, g_wgbh);
    cudaGetSymbolAddress((void**)&wgch, g_wgch);
    cudaGetSymbolAddress((void**)&wch,  g_wch);
    cudaGetSymbolAddress((void**)&weh,  g_weh);
    cudaGetSymbolAddress((void**)&wih,  g_wih);

    cudaFuncSetAttribute(mma_gemm<0,4,1,__half>,
        cudaFuncAttributeMaxDynamicSharedMemorySize, SMEM_NT4);
    cudaFuncSetAttribute(mma_gemm<5,4,1,__half>,
        cudaFuncAttributeMaxDynamicSharedMemorySize, SMEM_NT4);
    cudaFuncSetAttribute(mma_gemm<1,4,1,__half>,
        cudaFuncAttributeMaxDynamicSharedMemorySize, SMEM_NT4);
    cudaFuncSetAttribute(mma_gemm<0,4,1,float>,
        cudaFuncAttributeMaxDynamicSharedMemorySize, SMEM_NT4);
    cudaFuncSetAttribute(mma_gemm<0,2,KSP_,float>,
        cudaFuncAttributeMaxDynamicSharedMemorySize, SMEM_NT2);

    // 0. fp16-convert x and all weight matrices
    RoundJobs rj;
    rj.j[0] = { x,   xrh,  M_ * D_   / 4 };
    rj.j[1] = { Wa,  wah,  H2_ * D_  / 4 };
    rj.j[2] = { Wgb, wgbh, H_ * D_   / 4 };
    rj.j[3] = { Wgc, wgch, H_ * D_   / 4 };
    rj.j[4] = { Wc,  wch,  64 * H_   / 4 };
    rj.j[5] = { We,  weh,  H_ * 32   / 4 };
    rj.j[6] = { Wi,  wih,  D_ * H_   / 4 };
    round_all<<<dim3(1024, 7), 256>>>(rj);

    // 1. LayerNorm(ctx) -> fp16
    ln_kernel<<<M_, 256>>>(ctx, ln_w, ln_b, clnh);

    // 2. z = x @ Wa^T + ba                      [8192, 2048] fp16
    mma_gemm<0,4,1,__half><<<dim3(H2_ / 128, M_ / 128), 512, SMEM_NT4>>>(
        xrh, D_, wah, D_, ba, zh, H2_, D_,
        nullptr, nullptr, nullptr);

    // 3. merged gate GEMM -> p (cols<H) and q (cols>=H) fp16
    mma_gemm<5,4,1,__half><<<dim3(H2_ / 128, M_ / 128), 512, SMEM_NT4>>>(
        clnh, D_, wgbh, D_, bgb, ph, H_, D_,
        wgch, bgc, vh);

    // 4. fused uv + conv + silu -> uch fp16, v fp16 in-place over q
    uvconv_kernel<<<(int)(((size_t)M_ * H_ / 4 + 255) / 256), 256>>>(
        zh, ph, vh, conv_w, conv_b, uch);

    // 5. zc = uc @ Wc^T  (split-K over 4 chunks -> float partials, reduce)
    mma_gemm<0,2,KSP_,float><<<dim3(KSP_, M_ / 128), 512, SMEM_NT2>>>(
        uch, H_, wch, H_, nullptr, zcp, 64, H_,
        nullptr, nullptr, nullptr);
    zc_reduce<<<(M_ * 64 / 4 + 255) / 256, 256>>>(zcp, zcb, zch);

    // 6. dt = softplus(zc[:, :R] @ We^T + be)   [8192, 1024] fp16
    mma_gemm<1,4,1,__half><<<dim3(H_ / 128, M_ / 128), 512, SMEM_NT4>>>(
        zch, 64, weh, 32, be, dth, H_, 32,
        nullptr, nullptr, nullptr);

    // 7. selective scan (fused skip + silu(v) gate) -> fp16 yv
    scan_kernel<<<(B_ * H_ / 2) / 8, 256>>>(uch, dth, zcb, vh, f_log, g, yvh);

    // 8. out = yv @ Wi^T + bi                   [8192, 512] fp32
    mma_gemm<0,4,1,float><<<dim3(D_ / 128, M_ / 128), 512, SMEM_NT4>>>(
        yvh, H_, wih, H_, bi, out, D_, H_,
        nullptr, nullptr, nullptr);
}